// round 4
// baseline (speedup 1.0000x reference)
#include <cuda_runtime.h>
#include <cuda_bf16.h>

// VQ lookup: z[N,510] f32, codebook[128,510] f32 -> z_q[N,510] f32
// argmin_k (c_sq[k] - 2*z.c[k])  (z_sq dropped: constant per row)
//
// R3: double-buffered cp.async pipeline — prefetch chunk ch+1 while the
// f32x2 FMA loop computes chunk ch. Removes the serialized load phase that
// held fma pipe at 42.8%.

#define D_DIM   510
#define K_CODES 128
#define BM      64
#define DCHUNK  64
#define NCHUNK  8      // 8*64 = 512, padded with zeros
#define ZSTR    68     // smem row stride (floats); 68 mod 32 = 4 -> conflict-free LDS.128
#define CSTR    68

#define TILE_FLOATS (K_CODES*CSTR + BM*ZSTR)     // 13056 floats per buffer
#define RED_FLOATS  (8*BM + 8*BM + BM)           // redv, redk, kfin
#define SMEM_FLOATS (2*TILE_FLOATS + RED_FLOATS)
#define SMEM_BYTES  (SMEM_FLOATS * 4)

__device__ float g_csq[K_CODES];

// ---------------------------------------------------------------------------
__global__ void csq_kernel(const float* __restrict__ cb) {
    int k = blockIdx.x;
    int tid = threadIdx.x;
    float s = 0.f;
    for (int d = tid; d < D_DIM; d += 256) {
        float v = cb[k * D_DIM + d];
        s = fmaf(v, v, s);
    }
    #pragma unroll
    for (int off = 16; off; off >>= 1)
        s += __shfl_xor_sync(0xffffffffu, s, off);
    __shared__ float red[8];
    if ((tid & 31) == 0) red[tid >> 5] = s;
    __syncthreads();
    if (tid == 0) {
        float t = 0.f;
        #pragma unroll
        for (int i = 0; i < 8; i++) t += red[i];
        g_csq[k] = t;
    }
}

// Packed dual-FMA: d.lo += a.lo*b.lo ; d.hi += a.hi*b.hi
__device__ __forceinline__ void fma2(unsigned long long& d,
                                     unsigned long long a,
                                     unsigned long long b) {
    asm("fma.rn.f32x2 %0, %1, %2, %0;" : "+l"(d) : "l"(a), "l"(b));
}

__device__ __forceinline__ void cp_async8(unsigned dst, const void* src) {
    asm volatile("cp.async.ca.shared.global [%0], [%1], 8;"
                 :: "r"(dst), "l"(src));
}
__device__ __forceinline__ void cp_commit() {
    asm volatile("cp.async.commit_group;");
}
template <int N>
__device__ __forceinline__ void cp_wait() {
    asm volatile("cp.async.wait_group %0;" :: "n"(N));
}

extern __shared__ float smem[];

__global__ __launch_bounds__(256)
void vq_kernel(const float* __restrict__ z,
               const float* __restrict__ cb,
               float* __restrict__ out) {
    // smem carve: [buf0: cb|z][buf1: cb|z][redv][redk][kfin]
    float* redv  = smem + 2 * TILE_FLOATS;       // 8*64
    int*   redk  = (int*)(redv + 8 * BM);        // 8*64
    int*   kfin  = (int*)(redk + 8 * BM);        // 64

    const int tid  = threadIdx.x;
    const int wid  = tid >> 5;
    const int lane = tid & 31;
    const int tr   = lane >> 2;   // 0..7 : row-group within warp
    const int tc   = lane & 3;    // 0..3 : code-group within warp
    const long long row0 = (long long)blockIdx.x * BM;

    const float* zg = z + row0 * D_DIM;

    // per-thread load geometry (fixed across chunks)
    const int zr[8]  = { (0*256+tid)>>5, (1*256+tid)>>5, (2*256+tid)>>5, (3*256+tid)>>5,
                         (4*256+tid)>>5, (5*256+tid)>>5, (6*256+tid)>>5, (7*256+tid)>>5 };
    const int zdd    = (tid & 31) * 2;

    // shared-state base address (u32) for cp.async
    const unsigned smem_u32 = (unsigned)__cvta_generic_to_shared(smem);

    // tile loader: issues cp.async for chunk ch into buffer buf
    auto load_tile = [&](int buf, int ch) {
        const unsigned cb_base = smem_u32 + (unsigned)(buf * TILE_FLOATS) * 4u;
        const unsigned z_base  = cb_base + (unsigned)(K_CODES * CSTR) * 4u;
        const int dbase = ch * DCHUNK;
        const int gd = dbase + zdd;
        const bool ok = (gd < D_DIM);
        // z tile: 64 rows x 32 float2
        #pragma unroll
        for (int it = 0; it < 8; ++it) {
            const int r = zr[it];
            const unsigned dst = z_base + (unsigned)(r * ZSTR + zdd) * 4u;
            if (ok) cp_async8(dst, zg + (long long)r * D_DIM + gd);
            else {
                float2 zero = make_float2(0.f, 0.f);
                asm volatile("st.shared.v2.f32 [%0], {%1, %2};"
                             :: "r"(dst), "f"(zero.x), "f"(zero.y));
            }
        }
        // codebook tile: 128 rows x 32 float2 (L2-hot)
        #pragma unroll
        for (int it = 0; it < 16; ++it) {
            const int c = it * 8 + wid;                 // (it*256+tid)>>5
            const unsigned dst = cb_base + (unsigned)(c * CSTR + zdd) * 4u;
            if (ok) cp_async8(dst, cb + c * D_DIM + gd);
            else {
                float2 zero = make_float2(0.f, 0.f);
                asm volatile("st.shared.v2.f32 [%0], {%1, %2};"
                             :: "r"(dst), "f"(zero.x), "f"(zero.y));
            }
        }
        cp_commit();
    };

    unsigned long long acc[8][4];
    #pragma unroll
    for (int j = 0; j < 8; j++)
        #pragma unroll
        for (int cc = 0; cc < 4; cc++) acc[j][cc] = 0ull;

    load_tile(0, 0);

    for (int ch = 0; ch < NCHUNK; ++ch) {
        if (ch + 1 < NCHUNK) { load_tile((ch + 1) & 1, ch + 1); cp_wait<1>(); }
        else                 { cp_wait<0>(); }
        __syncthreads();

        const float* cb_s = smem + (ch & 1) * TILE_FLOATS;
        const float* z_s  = cb_s + K_CODES * CSTR;
        const float* zp = z_s + tr * ZSTR;                 // rows tr + 8j
        const float* cp = cb_s + (wid * 16 + tc) * CSTR;   // codes wid*16 + cc*4 + tc

        #pragma unroll 4
        for (int step = 0; step < 16; ++step) {
            const int d2 = step * 4;
            ulonglong2 cfr[4];
            #pragma unroll
            for (int cc = 0; cc < 4; ++cc)
                cfr[cc] = *(const ulonglong2*)(cp + cc * (4 * CSTR) + d2);
            #pragma unroll
            for (int j = 0; j < 8; ++j) {
                ulonglong2 zv = *(const ulonglong2*)(zp + j * (8 * ZSTR) + d2);
                #pragma unroll
                for (int cc = 0; cc < 4; ++cc) {
                    fma2(acc[j][cc], zv.x, cfr[cc].x);
                    fma2(acc[j][cc], zv.y, cfr[cc].y);
                }
            }
        }
        __syncthreads();   // all warps done with buf (ch&1) before it is refilled
    }

    float csqr[4];
    #pragma unroll
    for (int cc = 0; cc < 4; ++cc)
        csqr[cc] = g_csq[wid * 16 + cc * 4 + tc];

    // per-thread argmin over its 4 codes, then shuffle-reduce over tc
    #pragma unroll
    for (int j = 0; j < 8; ++j) {
        const int r = tr + 8 * j;
        float bv = 3.4e38f;
        int   bk = 0;
        #pragma unroll
        for (int cc = 0; cc < 4; ++cc) {
            unsigned long long a = acc[j][cc];
            float lo = __uint_as_float((unsigned)a);
            float hi = __uint_as_float((unsigned)(a >> 32));
            float dot = lo + hi;
            float d2v = fmaf(-2.f, dot, csqr[cc]);   // c_sq - 2*dot
            int c = wid * 16 + cc * 4 + tc;
            if (d2v < bv || (d2v == bv && c < bk)) { bv = d2v; bk = c; }
        }
        #pragma unroll
        for (int off = 1; off <= 2; off <<= 1) {
            float ov = __shfl_xor_sync(0xffffffffu, bv, off);
            int   ok = __shfl_xor_sync(0xffffffffu, bk, off);
            if (ov < bv || (ov == bv && ok < bk)) { bv = ov; bk = ok; }
        }
        if (tc == 0) { redv[wid * BM + r] = bv; redk[wid * BM + r] = bk; }
    }
    __syncthreads();

    // final argmin across the 8 warps' code groups
    if (tid < BM) {
        float bv = redv[tid];
        int   bk = redk[tid];
        #pragma unroll
        for (int w = 1; w < 8; ++w) {
            float ov = redv[w * BM + tid];
            int   ok = redk[w * BM + tid];
            if (ov < bv || (ov == bv && ok < bk)) { bv = ov; bk = ok; }
        }
        kfin[tid] = bk;
    }
    __syncthreads();

    // gather: out[row] = codebook[kfin[row]]  (codebook rows are L2-hot)
    if (tid < 255) {
        const int dpos = tid * 2;             // 255 float2 = 510 floats
        float* ob = out + row0 * D_DIM + dpos;
        #pragma unroll 8
        for (int r = 0; r < BM; ++r) {
            int k = kfin[r];
            float2 v = *(const float2*)(cb + k * D_DIM + dpos);
            *(float2*)(ob + (long long)r * D_DIM) = v;
        }
    }
}

extern "C" void kernel_launch(void* const* d_in, const int* in_sizes, int n_in,
                              void* d_out, int out_size) {
    const float* z  = (const float*)d_in[0];
    const float* cb = (const float*)d_in[1];
    float* out = (float*)d_out;

    cudaFuncSetAttribute(vq_kernel, cudaFuncAttributeMaxDynamicSharedMemorySize,
                         SMEM_BYTES);

    const int n_rows = in_sizes[0] / D_DIM;       // 131072
    const int nblocks = n_rows / BM;              // 2048

    csq_kernel<<<K_CODES, 256>>>(cb);
    vq_kernel<<<nblocks, 256, SMEM_BYTES>>>(z, cb, out);
}

// round 5
// speedup vs baseline: 1.0018x; 1.0018x over previous
#include <cuda_runtime.h>
#include <cuda_bf16.h>

// VQ lookup: z[N,510] f32, codebook[128,510] f32 -> z_q[N,510] f32
// argmin_k (c_sq[k] - 2*z.c[k])  (z_sq dropped: constant per row)
//
// R3: double-buffered cp.async pipeline — prefetch chunk ch+1 while the
// f32x2 FMA loop computes chunk ch. Removes the serialized load phase that
// held fma pipe at 42.8%.

#define D_DIM   510
#define K_CODES 128
#define BM      64
#define DCHUNK  64
#define NCHUNK  8      // 8*64 = 512, padded with zeros
#define ZSTR    68     // smem row stride (floats); 68 mod 32 = 4 -> conflict-free LDS.128
#define CSTR    68

#define TILE_FLOATS (K_CODES*CSTR + BM*ZSTR)     // 13056 floats per buffer
#define RED_FLOATS  (8*BM + 8*BM + BM)           // redv, redk, kfin
#define SMEM_FLOATS (2*TILE_FLOATS + RED_FLOATS)
#define SMEM_BYTES  (SMEM_FLOATS * 4)

__device__ float g_csq[K_CODES];

// ---------------------------------------------------------------------------
__global__ void csq_kernel(const float* __restrict__ cb) {
    int k = blockIdx.x;
    int tid = threadIdx.x;
    float s = 0.f;
    for (int d = tid; d < D_DIM; d += 256) {
        float v = cb[k * D_DIM + d];
        s = fmaf(v, v, s);
    }
    #pragma unroll
    for (int off = 16; off; off >>= 1)
        s += __shfl_xor_sync(0xffffffffu, s, off);
    __shared__ float red[8];
    if ((tid & 31) == 0) red[tid >> 5] = s;
    __syncthreads();
    if (tid == 0) {
        float t = 0.f;
        #pragma unroll
        for (int i = 0; i < 8; i++) t += red[i];
        g_csq[k] = t;
    }
}

// Packed dual-FMA: d.lo += a.lo*b.lo ; d.hi += a.hi*b.hi
__device__ __forceinline__ void fma2(unsigned long long& d,
                                     unsigned long long a,
                                     unsigned long long b) {
    asm("fma.rn.f32x2 %0, %1, %2, %0;" : "+l"(d) : "l"(a), "l"(b));
}

__device__ __forceinline__ void cp_async8(unsigned dst, const void* src) {
    asm volatile("cp.async.ca.shared.global [%0], [%1], 8;"
                 :: "r"(dst), "l"(src));
}
__device__ __forceinline__ void cp_commit() {
    asm volatile("cp.async.commit_group;");
}
template <int N>
__device__ __forceinline__ void cp_wait() {
    asm volatile("cp.async.wait_group %0;" :: "n"(N));
}

extern __shared__ float smem[];

__global__ __launch_bounds__(256)
void vq_kernel(const float* __restrict__ z,
               const float* __restrict__ cb,
               float* __restrict__ out) {
    // smem carve: [buf0: cb|z][buf1: cb|z][redv][redk][kfin]
    float* redv  = smem + 2 * TILE_FLOATS;       // 8*64
    int*   redk  = (int*)(redv + 8 * BM);        // 8*64
    int*   kfin  = (int*)(redk + 8 * BM);        // 64

    const int tid  = threadIdx.x;
    const int wid  = tid >> 5;
    const int lane = tid & 31;
    const int tr   = lane >> 2;   // 0..7 : row-group within warp
    const int tc   = lane & 3;    // 0..3 : code-group within warp
    const long long row0 = (long long)blockIdx.x * BM;

    const float* zg = z + row0 * D_DIM;

    // per-thread load geometry (fixed across chunks)
    const int zr[8]  = { (0*256+tid)>>5, (1*256+tid)>>5, (2*256+tid)>>5, (3*256+tid)>>5,
                         (4*256+tid)>>5, (5*256+tid)>>5, (6*256+tid)>>5, (7*256+tid)>>5 };
    const int zdd    = (tid & 31) * 2;

    // shared-state base address (u32) for cp.async
    const unsigned smem_u32 = (unsigned)__cvta_generic_to_shared(smem);

    // tile loader: issues cp.async for chunk ch into buffer buf
    auto load_tile = [&](int buf, int ch) {
        const unsigned cb_base = smem_u32 + (unsigned)(buf * TILE_FLOATS) * 4u;
        const unsigned z_base  = cb_base + (unsigned)(K_CODES * CSTR) * 4u;
        const int dbase = ch * DCHUNK;
        const int gd = dbase + zdd;
        const bool ok = (gd < D_DIM);
        // z tile: 64 rows x 32 float2
        #pragma unroll
        for (int it = 0; it < 8; ++it) {
            const int r = zr[it];
            const unsigned dst = z_base + (unsigned)(r * ZSTR + zdd) * 4u;
            if (ok) cp_async8(dst, zg + (long long)r * D_DIM + gd);
            else {
                float2 zero = make_float2(0.f, 0.f);
                asm volatile("st.shared.v2.f32 [%0], {%1, %2};"
                             :: "r"(dst), "f"(zero.x), "f"(zero.y));
            }
        }
        // codebook tile: 128 rows x 32 float2 (L2-hot)
        #pragma unroll
        for (int it = 0; it < 16; ++it) {
            const int c = it * 8 + wid;                 // (it*256+tid)>>5
            const unsigned dst = cb_base + (unsigned)(c * CSTR + zdd) * 4u;
            if (ok) cp_async8(dst, cb + c * D_DIM + gd);
            else {
                float2 zero = make_float2(0.f, 0.f);
                asm volatile("st.shared.v2.f32 [%0], {%1, %2};"
                             :: "r"(dst), "f"(zero.x), "f"(zero.y));
            }
        }
        cp_commit();
    };

    unsigned long long acc[8][4];
    #pragma unroll
    for (int j = 0; j < 8; j++)
        #pragma unroll
        for (int cc = 0; cc < 4; cc++) acc[j][cc] = 0ull;

    load_tile(0, 0);

    for (int ch = 0; ch < NCHUNK; ++ch) {
        if (ch + 1 < NCHUNK) { load_tile((ch + 1) & 1, ch + 1); cp_wait<1>(); }
        else                 { cp_wait<0>(); }
        __syncthreads();

        const float* cb_s = smem + (ch & 1) * TILE_FLOATS;
        const float* z_s  = cb_s + K_CODES * CSTR;
        const float* zp = z_s + tr * ZSTR;                 // rows tr + 8j
        const float* cp = cb_s + (wid * 16 + tc) * CSTR;   // codes wid*16 + cc*4 + tc

        #pragma unroll 4
        for (int step = 0; step < 16; ++step) {
            const int d2 = step * 4;
            ulonglong2 cfr[4];
            #pragma unroll
            for (int cc = 0; cc < 4; ++cc)
                cfr[cc] = *(const ulonglong2*)(cp + cc * (4 * CSTR) + d2);
            #pragma unroll
            for (int j = 0; j < 8; ++j) {
                ulonglong2 zv = *(const ulonglong2*)(zp + j * (8 * ZSTR) + d2);
                #pragma unroll
                for (int cc = 0; cc < 4; ++cc) {
                    fma2(acc[j][cc], zv.x, cfr[cc].x);
                    fma2(acc[j][cc], zv.y, cfr[cc].y);
                }
            }
        }
        __syncthreads();   // all warps done with buf (ch&1) before it is refilled
    }

    float csqr[4];
    #pragma unroll
    for (int cc = 0; cc < 4; ++cc)
        csqr[cc] = g_csq[wid * 16 + cc * 4 + tc];

    // per-thread argmin over its 4 codes, then shuffle-reduce over tc
    #pragma unroll
    for (int j = 0; j < 8; ++j) {
        const int r = tr + 8 * j;
        float bv = 3.4e38f;
        int   bk = 0;
        #pragma unroll
        for (int cc = 0; cc < 4; ++cc) {
            unsigned long long a = acc[j][cc];
            float lo = __uint_as_float((unsigned)a);
            float hi = __uint_as_float((unsigned)(a >> 32));
            float dot = lo + hi;
            float d2v = fmaf(-2.f, dot, csqr[cc]);   // c_sq - 2*dot
            int c = wid * 16 + cc * 4 + tc;
            if (d2v < bv || (d2v == bv && c < bk)) { bv = d2v; bk = c; }
        }
        #pragma unroll
        for (int off = 1; off <= 2; off <<= 1) {
            float ov = __shfl_xor_sync(0xffffffffu, bv, off);
            int   ok = __shfl_xor_sync(0xffffffffu, bk, off);
            if (ov < bv || (ov == bv && ok < bk)) { bv = ov; bk = ok; }
        }
        if (tc == 0) { redv[wid * BM + r] = bv; redk[wid * BM + r] = bk; }
    }
    __syncthreads();

    // final argmin across the 8 warps' code groups
    if (tid < BM) {
        float bv = redv[tid];
        int   bk = redk[tid];
        #pragma unroll
        for (int w = 1; w < 8; ++w) {
            float ov = redv[w * BM + tid];
            int   ok = redk[w * BM + tid];
            if (ov < bv || (ov == bv && ok < bk)) { bv = ov; bk = ok; }
        }
        kfin[tid] = bk;
    }
    __syncthreads();

    // gather: out[row] = codebook[kfin[row]]  (codebook rows are L2-hot)
    if (tid < 255) {
        const int dpos = tid * 2;             // 255 float2 = 510 floats
        float* ob = out + row0 * D_DIM + dpos;
        #pragma unroll 8
        for (int r = 0; r < BM; ++r) {
            int k = kfin[r];
            float2 v = *(const float2*)(cb + k * D_DIM + dpos);
            *(float2*)(ob + (long long)r * D_DIM) = v;
        }
    }
}

extern "C" void kernel_launch(void* const* d_in, const int* in_sizes, int n_in,
                              void* d_out, int out_size) {
    const float* z  = (const float*)d_in[0];
    const float* cb = (const float*)d_in[1];
    float* out = (float*)d_out;

    cudaFuncSetAttribute(vq_kernel, cudaFuncAttributeMaxDynamicSharedMemorySize,
                         SMEM_BYTES);

    const int n_rows = in_sizes[0] / D_DIM;       // 131072
    const int nblocks = n_rows / BM;              // 2048

    csq_kernel<<<K_CODES, 256>>>(cb);
    vq_kernel<<<nblocks, 256, SMEM_BYTES>>>(z, cb, out);
}

// round 6
// speedup vs baseline: 1.2218x; 1.2197x over previous
#include <cuda_runtime.h>
#include <cuda_bf16.h>

// VQ lookup: z[N,510] f32, codebook[128,510] f32 -> z_q[N,510] f32
// argmin_k (c_sq[k] - 2*z.c[k]) ; out = codebook[argmin]
//
// R5: rebalanced register tile 8 rows x 8 codes (was 8x4).
// Per warp-step: 16 LDS.128 (64 crossbar cyc) vs 128 FFMA2 (512 fma cyc/SM)
// -> smem crossbar and fma pipe balanced (R2/R3 were crossbar-bound at 67%).
// CTA = 128 rows x 128 codes, 256 threads, synchronous smem tile loads.

#define D_DIM   510
#define K_CODES 128
#define BM      128
#define DCHUNK  64
#define NCHUNK  8      // 8*64 = 512, padded with zeros
#define ZSTR    68     // row stride (floats): 272B -> tr rows hit distinct bank quads
#define CSTR    68

#define TILE_FLOATS (K_CODES*CSTR + BM*ZSTR)           // 17408 floats
#define RED_FLOATS  (4*BM + 4*BM + BM)                 // redv, redk, kfin
#define SMEM_FLOATS (TILE_FLOATS + RED_FLOATS)
#define SMEM_BYTES  (SMEM_FLOATS * 4)

__device__ float g_csq[K_CODES];

// ---------------------------------------------------------------------------
__global__ void csq_kernel(const float* __restrict__ cb) {
    int k = blockIdx.x;
    int tid = threadIdx.x;
    float s = 0.f;
    for (int d = tid; d < D_DIM; d += 256) {
        float v = cb[k * D_DIM + d];
        s = fmaf(v, v, s);
    }
    #pragma unroll
    for (int off = 16; off; off >>= 1)
        s += __shfl_xor_sync(0xffffffffu, s, off);
    __shared__ float red[8];
    if ((tid & 31) == 0) red[tid >> 5] = s;
    __syncthreads();
    if (tid == 0) {
        float t = 0.f;
        #pragma unroll
        for (int i = 0; i < 8; i++) t += red[i];
        g_csq[k] = t;
    }
}

// Packed dual-FMA: d.lo += a.lo*b.lo ; d.hi += a.hi*b.hi
__device__ __forceinline__ void fma2(unsigned long long& d,
                                     unsigned long long a,
                                     unsigned long long b) {
    asm("fma.rn.f32x2 %0, %1, %2, %0;" : "+l"(d) : "l"(a), "l"(b));
}

extern __shared__ float smem[];

__global__ __launch_bounds__(256, 1)
void vq_kernel(const float* __restrict__ z,
               const float* __restrict__ cb,
               float* __restrict__ out) {
    // smem carve: [cb 128x68][z 128x68][redv 4x128][redk 4x128][kfin 128]
    float* cb_s  = smem;
    float* z_s   = cb_s + K_CODES * CSTR;
    float* redv  = z_s + BM * ZSTR;
    int*   redk  = (int*)(redv + 4 * BM);
    int*   kfin  = (int*)(redk + 4 * BM);

    const int tid   = threadIdx.x;
    const int wid   = tid >> 5;
    const int lane  = tid & 31;
    const int tr    = lane >> 2;          // 0..7 row group
    const int tc    = lane & 3;           // 0..3 code group
    const int rhalf = wid >> 2;           // 0/1 : row half (64 rows)
    const int wq    = wid & 3;            // 0..3 : code quarter (32 codes)
    const long long row0 = (long long)blockIdx.x * BM;

    const float* zg = z + row0 * D_DIM;

    unsigned long long acc[8][8];         // [row j][code cc] packed f32x2
    #pragma unroll
    for (int j = 0; j < 8; j++)
        #pragma unroll
        for (int cc = 0; cc < 8; cc++) acc[j][cc] = 0ull;

    const int ldd = (tid & 31) * 2;       // d-offset within chunk for loads

    for (int ch = 0; ch < NCHUNK; ++ch) {
        __syncthreads();
        const int gd = ch * DCHUNK + ldd;
        const bool ok = (gd < D_DIM);

        // z tile: 128 rows x 32 float2  (16 iters; row = it*8 + wid)
        #pragma unroll
        for (int it = 0; it < 16; ++it) {
            const int r = it * 8 + wid;
            float2 v = make_float2(0.f, 0.f);
            if (ok) v = *(const float2*)(zg + (long long)r * D_DIM + gd);
            *(float2*)(z_s + r * ZSTR + ldd) = v;
        }
        // codebook tile: 128 rows x 32 float2 (L2-hot)
        #pragma unroll
        for (int it = 0; it < 16; ++it) {
            const int c = it * 8 + wid;
            float2 v = make_float2(0.f, 0.f);
            if (ok) v = *(const float2*)(cb + c * D_DIM + gd);
            *(float2*)(cb_s + c * CSTR + ldd) = v;
        }
        __syncthreads();

        const float* zp = z_s + (rhalf * 64 + tr) * ZSTR;  // rows rhalf*64 + tr + 8j
        const float* cp = cb_s + (wq * 32 + tc) * CSTR;    // codes wq*32 + cc*4 + tc

        #pragma unroll 4
        for (int step = 0; step < 16; ++step) {
            const int d2 = step * 4;
            ulonglong2 cfr[8];
            #pragma unroll
            for (int cc = 0; cc < 8; ++cc)
                cfr[cc] = *(const ulonglong2*)(cp + cc * (4 * CSTR) + d2);
            #pragma unroll
            for (int j = 0; j < 8; ++j) {
                ulonglong2 zv = *(const ulonglong2*)(zp + j * (8 * ZSTR) + d2);
                #pragma unroll
                for (int cc = 0; cc < 8; ++cc) {
                    fma2(acc[j][cc], zv.x, cfr[cc].x);
                    fma2(acc[j][cc], zv.y, cfr[cc].y);
                }
            }
        }
    }

    float csqr[8];
    #pragma unroll
    for (int cc = 0; cc < 8; ++cc)
        csqr[cc] = g_csq[wq * 32 + cc * 4 + tc];

    // per-thread argmin over its 8 codes, shuffle-reduce over tc (4 lanes)
    #pragma unroll
    for (int j = 0; j < 8; ++j) {
        const int r = rhalf * 64 + tr + 8 * j;   // 0..127
        float bv = 3.4e38f;
        int   bk = 0;
        #pragma unroll
        for (int cc = 0; cc < 8; ++cc) {
            unsigned long long a = acc[j][cc];
            float lo = __uint_as_float((unsigned)a);
            float hi = __uint_as_float((unsigned)(a >> 32));
            float dot = lo + hi;
            float d2v = fmaf(-2.f, dot, csqr[cc]);   // c_sq - 2*dot
            int c = wq * 32 + cc * 4 + tc;
            if (d2v < bv || (d2v == bv && c < bk)) { bv = d2v; bk = c; }
        }
        #pragma unroll
        for (int off = 1; off <= 2; off <<= 1) {
            float ov = __shfl_xor_sync(0xffffffffu, bv, off);
            int   ok2 = __shfl_xor_sync(0xffffffffu, bk, off);
            if (ov < bv || (ov == bv && ok2 < bk)) { bv = ov; bk = ok2; }
        }
        if (tc == 0) { redv[wq * BM + r] = bv; redk[wq * BM + r] = bk; }
    }
    __syncthreads();

    // final argmin across the 4 code-quarter warps
    if (tid < BM) {
        float bv = redv[tid];
        int   bk = redk[tid];
        #pragma unroll
        for (int w = 1; w < 4; ++w) {
            float ov = redv[w * BM + tid];
            int   ok2 = redk[w * BM + tid];
            if (ov < bv || (ov == bv && ok2 < bk)) { bv = ov; bk = ok2; }
        }
        kfin[tid] = bk;
    }
    __syncthreads();

    // gather: out[row] = codebook[kfin[row]]  (codebook rows are L2-hot)
    if (tid < 255) {
        const int dpos = tid * 2;             // 255 float2 = 510 floats
        float* ob = out + row0 * D_DIM + dpos;
        #pragma unroll 4
        for (int r = 0; r < BM; ++r) {
            int k = kfin[r];
            float2 v = *(const float2*)(cb + k * D_DIM + dpos);
            *(float2*)(ob + (long long)r * D_DIM) = v;
        }
    }
}

extern "C" void kernel_launch(void* const* d_in, const int* in_sizes, int n_in,
                              void* d_out, int out_size) {
    const float* z  = (const float*)d_in[0];
    const float* cb = (const float*)d_in[1];
    float* out = (float*)d_out;

    cudaFuncSetAttribute(vq_kernel, cudaFuncAttributeMaxDynamicSharedMemorySize,
                         SMEM_BYTES);

    const int n_rows = in_sizes[0] / D_DIM;       // 131072
    const int nblocks = n_rows / BM;              // 1024

    csq_kernel<<<K_CODES, 256>>>(cb);
    vq_kernel<<<nblocks, 256, SMEM_BYTES>>>(z, cb, out);
}

// round 8
// speedup vs baseline: 1.6839x; 1.3782x over previous
#include <cuda_runtime.h>
#include <cuda_bf16.h>
#include <cstdint>

// VQ lookup via warp-level bf16 mma.sync (HMMA) + exact fp32 refinement.
//   dot(z,c) ~= zh*ch + zh*cl + zl*ch   (2-way bf16 Dekker split, 3 passes)
//   d2 = c_sq - 2*dot ; top-2 tracked ; gap < TAU -> exact fp32 re-argmin.
// (tcgen05 PTX is rejected by this toolchain's sm_103 ptxas target.)

#define D_DIM   510
#define K_CODES 128
#define BM      128
#define KC      64           // K-chunk (elements)
#define NCH     8            // 8*64 = 512, cols 510/511 zeroed
#define TAU     0.01f
#define ST      144          // smem tile row stride BYTES (72 bf16): 16B-aligned, 36 words

// smem byte offsets
#define SM_CSQ  0                        // 128 f32
#define SM_KF   512                      // 128 i32
#define SM_BV   1024                     // 2*128 f32
#define SM_SV   2048                     // 2*128 f32
#define SM_BK   3072                     // 2*128 i32
#define SM_ZH   4096                     // 128*ST
#define SM_ZL   (SM_ZH + 128*ST)
#define SM_CH   (SM_ZL + 128*ST)
#define SM_CL   (SM_CH + 128*ST)
#define SMEM_BYTES (SM_CL + 128*ST)      // 77824

__device__ float g_csq[K_CODES];
__device__ unsigned char g_flag[131072];

// ---------------------------------------------------------------- c_sq
__global__ void csq_kernel(const float* __restrict__ cb) {
    int k = blockIdx.x, tid = threadIdx.x;
    float s = 0.f;
    for (int d = tid; d < D_DIM; d += 256) {
        float v = cb[k * D_DIM + d];
        s = fmaf(v, v, s);
    }
    #pragma unroll
    for (int off = 16; off; off >>= 1) s += __shfl_xor_sync(0xffffffffu, s, off);
    __shared__ float red[8];
    if ((tid & 31) == 0) red[tid >> 5] = s;
    __syncthreads();
    if (tid == 0) {
        float t = 0.f;
        #pragma unroll
        for (int i = 0; i < 8; i++) t += red[i];
        g_csq[k] = t;
    }
}

// ---------------------------------------------------------------- helpers
__device__ __forceinline__ void split2(float x, __nv_bfloat16& h, __nv_bfloat16& l) {
    h = __float2bfloat16(x);
    l = __float2bfloat16(x - __bfloat162float(h));
}
__device__ __forceinline__ uint32_t pack2(__nv_bfloat16 a, __nv_bfloat16 b) {
    return (uint32_t)__bfloat16_as_ushort(b) << 16 | (uint32_t)__bfloat16_as_ushort(a);
}

__device__ __forceinline__ void ldm4(uint32_t* r, uint32_t addr) {
    asm volatile("ldmatrix.sync.aligned.m8n8.x4.shared.b16 {%0,%1,%2,%3}, [%4];"
                 : "=r"(r[0]), "=r"(r[1]), "=r"(r[2]), "=r"(r[3]) : "r"(addr));
}
__device__ __forceinline__ void mma16816(float* d, const uint32_t* a,
                                         const uint32_t* b) {
    asm volatile(
        "mma.sync.aligned.m16n8k16.row.col.f32.bf16.bf16.f32 "
        "{%0,%1,%2,%3}, {%4,%5,%6,%7}, {%8,%9}, {%0,%1,%2,%3};"
        : "+f"(d[0]), "+f"(d[1]), "+f"(d[2]), "+f"(d[3])
        : "r"(a[0]), "r"(a[1]), "r"(a[2]), "r"(a[3]), "r"(b[0]), "r"(b[1]));
}

// top-2 merge: (bv,sv,bk) <- merge with (obv,osv,obk)
__device__ __forceinline__ void merge2(float& bv, float& sv, int& bk,
                                       float obv, float osv, int obk) {
    if (obv < bv) { sv = fminf(bv, osv); bv = obv; bk = obk; }
    else          { sv = fminf(sv, obv); }
}

extern __shared__ __align__(128) char smem[];

// ---------------------------------------------------------------- main kernel
__global__ __launch_bounds__(256, 2)
void vq_mma_kernel(const float* __restrict__ z,
                   const float* __restrict__ cb,
                   float* __restrict__ out) {
    const uint32_t sbase = (uint32_t)__cvta_generic_to_shared(smem);
    const int tid  = threadIdx.x;
    const int wid  = tid >> 5;
    const int lane = tid & 31;
    const int wr   = wid & 3;       // row group: 4 x 32 rows
    const int wc   = wid >> 2;      // code group: 2 x 64 codes
    const long long row0 = (long long)blockIdx.x * BM;

    if (tid < K_CODES) *(float*)(smem + SM_CSQ + tid * 4) = g_csq[tid];

    const float* zg = z + row0 * D_DIM;

    float acc[2][8][4];             // [m-tile][n-tile][frag]
    #pragma unroll
    for (int mt = 0; mt < 2; ++mt)
        #pragma unroll
        for (int nt = 0; nt < 8; ++nt)
            #pragma unroll
            for (int q = 0; q < 4; ++q) acc[mt][nt][q] = 0.f;

    // ldmatrix lane->address geometry (byte offsets within tile)
    const uint32_t a_off = (uint32_t)((wr * 32 + (lane & 15)) * ST + ((lane >> 4) * 8) * 2);
    const uint32_t b_off = (uint32_t)((wc * 64 + ((lane >> 4) << 3) + (lane & 7)) * ST
                                      + (((lane >> 3) & 1) * 8) * 2);

    // load/convert geometry: 16 threads per row, 4 floats each
    const int lr0 = tid >> 4;        // +16 per iter (8 iters -> 128 rows)
    const int lkq = (tid & 15) * 4;  // 0,4,...,60

    for (int ch = 0; ch < NCH; ++ch) {
        __syncthreads();             // tiles free (prev chunk's mma done)
        const int gk = ch * KC + lkq;
        const bool tail = (gk == 508);    // last 4-group: cols 510,511 pad
        #pragma unroll
        for (int it = 0; it < 8; ++it) {
            const int r = lr0 + it * 16;
            const uint32_t so = (uint32_t)(r * ST + lkq * 2);
            {   // z tile
                const float* p = zg + (long long)r * D_DIM + gk;
                float2 a = *(const float2*)p;
                float2 b = tail ? make_float2(0.f, 0.f) : *(const float2*)(p + 2);
                __nv_bfloat16 h0,l0,h1,l1,h2,l2,h3,l3;
                split2(a.x,h0,l0); split2(a.y,h1,l1);
                split2(b.x,h2,l2); split2(b.y,h3,l3);
                *(uint2*)(smem + SM_ZH + so) = make_uint2(pack2(h0,h1), pack2(h2,h3));
                *(uint2*)(smem + SM_ZL + so) = make_uint2(pack2(l0,l1), pack2(l2,l3));
            }
            {   // codebook tile (L2-hot)
                const float* p = cb + r * D_DIM + gk;
                float2 a = *(const float2*)p;
                float2 b = tail ? make_float2(0.f, 0.f) : *(const float2*)(p + 2);
                __nv_bfloat16 h0,l0,h1,l1,h2,l2,h3,l3;
                split2(a.x,h0,l0); split2(a.y,h1,l1);
                split2(b.x,h2,l2); split2(b.y,h3,l3);
                *(uint2*)(smem + SM_CH + so) = make_uint2(pack2(h0,h1), pack2(h2,h3));
                *(uint2*)(smem + SM_CL + so) = make_uint2(pack2(l0,l1), pack2(l2,l3));
            }
        }
        __syncthreads();

        // ---- mma over 4 k-steps of 16
        #pragma unroll
        for (int ks = 0; ks < 4; ++ks) {
            const uint32_t kb = (uint32_t)(ks * 32);   // 16 bf16 = 32 bytes
            uint32_t ah[2][4], al[2][4];
            #pragma unroll
            for (int mt = 0; mt < 2; ++mt) {
                const uint32_t ao = a_off + (uint32_t)(mt * 16 * ST) + kb;
                ldm4(ah[mt], sbase + SM_ZH + ao);
                ldm4(al[mt], sbase + SM_ZL + ao);
            }
            #pragma unroll
            for (int np = 0; np < 4; ++np) {           // n-tile pairs
                const uint32_t bo = b_off + (uint32_t)(np * 16 * ST) + kb;
                uint32_t bh[4], bl[4];
                ldm4(bh, sbase + SM_CH + bo);
                ldm4(bl, sbase + SM_CL + bo);
                #pragma unroll
                for (int mt = 0; mt < 2; ++mt) {
                    mma16816(acc[mt][np*2+0], ah[mt], bh + 0);
                    mma16816(acc[mt][np*2+1], ah[mt], bh + 2);
                    mma16816(acc[mt][np*2+0], ah[mt], bl + 0);
                    mma16816(acc[mt][np*2+1], ah[mt], bl + 2);
                    mma16816(acc[mt][np*2+0], al[mt], bh + 0);
                    mma16816(acc[mt][np*2+1], al[mt], bh + 2);
                }
            }
        }
    }

    // ---- epilogue: top-2 per row
    const float* csq_s = (const float*)(smem + SM_CSQ);
    float* bvp = (float*)(smem + SM_BV);
    float* svp = (float*)(smem + SM_SV);
    int*   bkp = (int*)(smem + SM_BK);

    #pragma unroll
    for (int mt = 0; mt < 2; ++mt) {
        #pragma unroll
        for (int rh = 0; rh < 2; ++rh) {
            float bv = 3.4e38f, sv = 3.4e38f;
            int bk = 0;
            #pragma unroll
            for (int nt = 0; nt < 8; ++nt) {
                #pragma unroll
                for (int s = 0; s < 2; ++s) {
                    const int c = wc * 64 + nt * 8 + (lane & 3) * 2 + s;
                    const float d2 = fmaf(-2.f, acc[mt][nt][rh * 2 + s], csq_s[c]);
                    if (d2 < bv) { sv = bv; bv = d2; bk = c; }
                    else if (d2 < sv) sv = d2;
                }
            }
            #pragma unroll
            for (int off = 1; off <= 2; off <<= 1) {
                float obv = __shfl_xor_sync(0xffffffffu, bv, off);
                float osv = __shfl_xor_sync(0xffffffffu, sv, off);
                int   obk = __shfl_xor_sync(0xffffffffu, bk, off);
                merge2(bv, sv, bk, obv, osv, obk);
            }
            if ((lane & 3) == 0) {
                const int r = wr * 32 + mt * 16 + rh * 8 + (lane >> 2);
                bvp[wc * 128 + r] = bv;
                svp[wc * 128 + r] = sv;
                bkp[wc * 128 + r] = bk;
            }
        }
    }
    __syncthreads();

    if (tid < BM) {
        float bv = bvp[tid], sv = svp[tid];
        int bk = bkp[tid];
        merge2(bv, sv, bk, bvp[128 + tid], svp[128 + tid], bkp[128 + tid]);
        *(int*)(smem + SM_KF + tid * 4) = bk;
        g_flag[row0 + tid] = ((sv - bv) < TAU) ? 1 : 0;
    }
    __syncthreads();

    // ---- gather: out[row] = codebook[kfin[row]]
    if (tid < 255) {
        const int dpos = tid * 2;
        float* ob = out + row0 * D_DIM + dpos;
        #pragma unroll 4
        for (int r = 0; r < BM; ++r) {
            int k = *(const int*)(smem + SM_KF + r * 4);
            float2 v = *(const float2*)(cb + k * D_DIM + dpos);
            *(float2*)(ob + (long long)r * D_DIM) = v;
        }
    }
}

// ---------------------------------------------------------------- exact refinement
__global__ __launch_bounds__(256)
void refine_kernel(const float* __restrict__ z,
                   const float* __restrict__ cb,
                   float* __restrict__ out) {
    const int tid = threadIdx.x, wid = tid >> 5, lane = tid & 31;
    const long long row0 = (long long)blockIdx.x * BM;
    for (int j = 0; j < 16; ++j) {
        const long long row = row0 + wid * 16 + j;
        if (!g_flag[row]) continue;                 // warp-uniform
        const float* zr = z + row * D_DIM;
        float zreg[16];
        #pragma unroll
        for (int t = 0; t < 16; ++t) {
            int d = lane + t * 32;
            zreg[t] = (d < D_DIM) ? zr[d] : 0.f;
        }
        float bv = 3.4e38f;
        int bk = 0;
        for (int c = 0; c < K_CODES; ++c) {
            const float* cr = cb + c * D_DIM;
            float s = 0.f;
            #pragma unroll
            for (int t = 0; t < 16; ++t) {
                int d = lane + t * 32;
                float cv = (d < D_DIM) ? cr[d] : 0.f;
                s = fmaf(zreg[t], cv, s);
            }
            #pragma unroll
            for (int off = 16; off; off >>= 1)
                s += __shfl_xor_sync(0xffffffffu, s, off);
            float d2 = fmaf(-2.f, s, g_csq[c]);
            if (d2 < bv) { bv = d2; bk = c; }       // strict < : lowest index wins ties
        }
        for (int d = lane; d < D_DIM; d += 32)
            out[row * D_DIM + d] = cb[bk * D_DIM + d];
    }
}

// ---------------------------------------------------------------- launch
extern "C" void kernel_launch(void* const* d_in, const int* in_sizes, int n_in,
                              void* d_out, int out_size) {
    const float* z  = (const float*)d_in[0];
    const float* cb = (const float*)d_in[1];
    float* out = (float*)d_out;

    cudaFuncSetAttribute(vq_mma_kernel, cudaFuncAttributeMaxDynamicSharedMemorySize,
                         SMEM_BYTES);

    const int n_rows  = in_sizes[0] / D_DIM;   // 131072
    const int nblocks = n_rows / BM;           // 1024

    csq_kernel<<<K_CODES, 256>>>(cb);
    vq_mma_kernel<<<nblocks, 256, SMEM_BYTES>>>(z, cb, out);
    refine_kernel<<<nblocks, 256>>>(z, cb, out);
}